// round 1
// baseline (speedup 1.0000x reference)
#include <cuda_runtime.h>
#include <cstddef>

// GaussianIntegral2D: per (b1,b2) pair, rotate+translate 49 quadrature points,
// evaluate 2D-MVN logpdf at each, weighted-sum of exp(logp), clip to [0,1].
// Output buffer = [gauss_pts: B1*B2*49*2 f32][integral: B1*B2 f32].
//
// One warp per pair. Lane l covers q = l and q = l + 32 (Q = 49).
// Stores: 49 contiguous float2 per pair -> fully coalesced.

#define LOG2PI_F 1.8378770664093453f

static constexpr int Q = 49;

__global__ void __launch_bounds__(256)
gauss_integral_kernel(const float* __restrict__ means,   // [P,2]
                      const float* __restrict__ covars,  // [P,2,2]
                      const float* __restrict__ rots,    // [P,2,2]
                      const float* __restrict__ trans,   // [P,2]
                      const float* __restrict__ eta,     // [2,Q]
                      const float* __restrict__ wts,     // [Q]
                      float* __restrict__ out_pts,       // [P,Q,2]
                      float* __restrict__ out_int,       // [P]
                      int npair)
{
    const int lane = threadIdx.x & 31;
    const int warp = (int)((blockIdx.x * blockDim.x + threadIdx.x) >> 5);
    const int nwarp = (int)((gridDim.x * blockDim.x) >> 5);

    // Quadrature values held in registers (loop-invariant).
    const int q0 = lane;
    const int q1 = lane + 32;
    const bool has1 = (q1 < Q);
    const float ex0 = eta[q0];
    const float ey0 = eta[Q + q0];
    const float w0  = wts[q0];
    float ex1 = 0.f, ey1 = 0.f, w1 = 0.f;
    if (has1) { ex1 = eta[q1]; ey1 = eta[Q + q1]; w1 = wts[q1]; }

    for (int p = warp; p < npair; p += nwarp) {
        // Uniform-address vector loads (broadcast within the warp).
        const float2 m = reinterpret_cast<const float2*>(means)[p];
        const float4 c = reinterpret_cast<const float4*>(covars)[p]; // c00 c01 c10 c11
        const float4 r = reinterpret_cast<const float4*>(rots)[p];   // r00 r01 r10 r11
        const float2 t = reinterpret_cast<const float2*>(trans)[p];

        const float det    = c.x * c.w - c.y * c.z;
        const float invdet = __frcp_rn(det);
        const float base   = fmaf(-0.5f, __logf(det), -LOG2PI_F);
        const float csum   = c.y + c.z;

        // Rotated + translated quadrature points.
        const float px0 = fmaf(r.x, ex0, fmaf(r.y, ey0, t.x));
        const float py0 = fmaf(r.z, ex0, fmaf(r.w, ey0, t.y));
        const float px1 = fmaf(r.x, ex1, fmaf(r.y, ey1, t.x));
        const float py1 = fmaf(r.z, ex1, fmaf(r.w, ey1, t.y));

        float2* po = reinterpret_cast<float2*>(out_pts + (size_t)p * (size_t)(2 * Q));
        po[q0] = make_float2(px0, py0);
        if (has1) po[q1] = make_float2(px1, py1);

        // MVN logpdf -> exp -> weighted sum.
        float dx = px0 - m.x, dy = py0 - m.y;
        float quad = (c.w * dx * dx - csum * dx * dy + c.x * dy * dy) * invdet;
        float val = __expf(fmaf(-0.5f, quad, base)) * w0;
        if (has1) {
            dx = px1 - m.x; dy = py1 - m.y;
            quad = (c.w * dx * dx - csum * dx * dy + c.x * dy * dy) * invdet;
            val += __expf(fmaf(-0.5f, quad, base)) * w1;
        }

        // Warp reduction over all 49 contributions.
        #pragma unroll
        for (int off = 16; off; off >>= 1)
            val += __shfl_down_sync(0xffffffffu, val, off);

        if (lane == 0)
            out_int[p] = fminf(fmaxf(val, 0.0f), 1.0f);
    }
}

extern "C" void kernel_launch(void* const* d_in, const int* in_sizes, int n_in,
                              void* d_out, int out_size)
{
    const float* means  = (const float*)d_in[0]; // tv_means   [P,2]
    const float* covars = (const float*)d_in[1]; // tv_covars  [P,2,2]
    const float* rots   = (const float*)d_in[2]; // rotations  [P,2,2]
    const float* trans  = (const float*)d_in[3]; // translations [P,2]
    const float* eta    = (const float*)d_in[4]; // eta_01 [2,Q]
    const float* wts    = (const float*)d_in[5]; // weights [Q]

    const int npair = in_sizes[0] / 2;           // B1*B2

    float* out_pts = (float*)d_out;
    float* out_int = out_pts + (size_t)npair * (size_t)(2 * Q);

    // One warp per pair: 8 warps per 256-thread block.
    const int blocks = (npair + 7) / 8;
    gauss_integral_kernel<<<blocks, 256>>>(means, covars, rots, trans,
                                           eta, wts, out_pts, out_int, npair);
}

// round 2
// speedup vs baseline: 1.9938x; 1.9938x over previous
#include <cuda_runtime.h>
#include <cstddef>

// GaussianIntegral2D — thread-per-pair with warp-local smem staging.
//
// Each thread owns one (b1,b2) pair: loads its 12 params via coalesced
// per-lane float2/float4 LDGs, iterates the 49 quadrature points computing
// (px,py) + the MVN integrand, writes points into its warp's smem tile
// (conflict-free STS.64), accumulates the integral in registers (no shuffles).
// Then the warp cooperatively streams its 32*98-float tile to global as
// coalesced float4 stores. Output = [pts: P*49*2 f32][integral: P f32].

#define LOG2PI_F 1.8378770664093453f

static constexpr int Q        = 49;
static constexpr int TPB      = 256;
static constexpr int WARPS    = TPB / 32;
static constexpr int TILE_F   = 32 * 2 * Q;              // floats per warp tile (3136)
static constexpr int QD_OFF_F = WARPS * TILE_F;          // qd table offset (floats)
static constexpr size_t SMEM_BYTES = (size_t)QD_OFF_F * 4 + 64 * 16;

__global__ void __launch_bounds__(TPB)
gauss_integral_kernel(const float* __restrict__ means,   // [P,2]
                      const float* __restrict__ covars,  // [P,4]
                      const float* __restrict__ rots,    // [P,4]
                      const float* __restrict__ trans,   // [P,2]
                      const float* __restrict__ eta,     // [2,Q]
                      const float* __restrict__ wts,     // [Q]
                      float* __restrict__ out_pts,       // [P,Q,2]
                      float* __restrict__ out_int,       // [P]
                      int npair)
{
    extern __shared__ float sm[];
    float4* qd = reinterpret_cast<float4*>(sm + QD_OFF_F);

    const int tid  = threadIdx.x;
    const int lane = tid & 31;
    const int wid  = tid >> 5;

    // Stage quadrature table once per block: {ex, ey, w, 0} per point.
    if (tid < Q)
        qd[tid] = make_float4(eta[tid], eta[Q + tid], wts[tid], 0.0f);
    __syncthreads();

    const int p        = blockIdx.x * TPB + tid;   // this thread's pair
    const int tilebase = blockIdx.x * TPB + (wid << 5);
    float* row = sm + wid * TILE_F + lane * (2 * Q);

    if (p < npair) {
        // Coalesced per-lane parameter loads.
        const float2 m = reinterpret_cast<const float2*>(means)[p];
        const float4 c = reinterpret_cast<const float4*>(covars)[p]; // c00 c01 c10 c11
        const float4 r = reinterpret_cast<const float4*>(rots)[p];
        const float2 t = reinterpret_cast<const float2*>(trans)[p];

        const float det    = c.x * c.w - c.y * c.z;
        const float kinv   = -0.5f * __frcp_rn(det);         // folds -0.5 * det^-1
        const float base   = fmaf(-0.5f, __logf(det), -LOG2PI_F);
        const float csum   = c.y + c.z;

        float acc0 = 0.0f, acc1 = 0.0f;

        #pragma unroll 7
        for (int q = 0; q < Q; ++q) {
            const float4 e = qd[q];                           // broadcast LDS.128
            const float px = fmaf(r.x, e.x, fmaf(r.y, e.y, t.x));
            const float py = fmaf(r.z, e.x, fmaf(r.w, e.y, t.y));
            reinterpret_cast<float2*>(row)[q] = make_float2(px, py); // STS.64, bank-clean

            const float dx = px - m.x, dy = py - m.y;
            const float quad = fmaf(c.w * dx, dx,
                               fmaf(-csum * dx, dy, c.x * dy * dy));
            const float v = __expf(fmaf(kinv, quad, base)) * e.z;
            if (q & 1) acc1 += v; else acc0 += v;
        }

        out_int[p] = fminf(fmaxf(acc0 + acc1, 0.0f), 1.0f);  // coalesced
    }

    __syncwarp();

    // Warp-cooperative coalesced copy-out of this warp's tile.
    const float4* src = reinterpret_cast<const float4*>(sm + wid * TILE_F);
    const int rem_pairs = npair - tilebase;
    if (rem_pairs >= 32) {
        // Full tile: 3136 floats = 784 float4.
        float4* dst = reinterpret_cast<float4*>(out_pts + (size_t)tilebase * (2 * Q));
        #pragma unroll 4
        for (int i = lane; i < TILE_F / 4; i += 32)
            __stcs(dst + i, src[i]);
    } else if (rem_pairs > 0) {
        // Tail tile: per-float copy (never hit for P = 524288).
        const int nf = rem_pairs * 2 * Q;
        const float* s = sm + wid * TILE_F;
        float* d = out_pts + (size_t)tilebase * (2 * Q);
        for (int i = lane; i < nf; i += 32) d[i] = s[i];
    }
}

extern "C" void kernel_launch(void* const* d_in, const int* in_sizes, int n_in,
                              void* d_out, int out_size)
{
    const float* means  = (const float*)d_in[0];
    const float* covars = (const float*)d_in[1];
    const float* rots   = (const float*)d_in[2];
    const float* trans  = (const float*)d_in[3];
    const float* eta    = (const float*)d_in[4];
    const float* wts    = (const float*)d_in[5];

    const int npair = in_sizes[0] / 2;

    float* out_pts = (float*)d_out;
    float* out_int = out_pts + (size_t)npair * (size_t)(2 * Q);

    cudaFuncSetAttribute(gauss_integral_kernel,
                         cudaFuncAttributeMaxDynamicSharedMemorySize,
                         (int)SMEM_BYTES);

    const int blocks = (npair + TPB - 1) / TPB;
    gauss_integral_kernel<<<blocks, TPB, SMEM_BYTES>>>(
        means, covars, rots, trans, eta, wts, out_pts, out_int, npair);
}